// round 11
// baseline (speedup 1.0000x reference)
#include <cuda_runtime.h>
#include <cuda_bf16.h>
#include <math.h>

// Problem dims
#define B_ 8
#define L_ 512
#define D_ 512
#define H_ 8
#define DH_ 64
#define NROWS 4096          // B*L
#define NPAD 1664           // 512(q)+512(k)+512(v)+24(p) padded (13*128)
#define KP 1536             // split-GEMM K' = 3*512

// Output layout (concatenated fp32): readout | state_seq | mom_seq
#define OFF_S 2097152UL
#define OFF_M 136314880UL

// Packed per-(b,h) stream: [q(64) | k_norm(64) | v(64) | gates@192 | pad] per step
// 256 floats = 1024 B -> every substream sector-aligned.
#define PSTEP 256

// Scratch (static device arrays — no allocation)
__device__ __nv_bfloat16 g_A2[(size_t)NROWS * KP];   // [Ahi | Ahi | Alo] rows
__device__ __nv_bfloat16 g_B2T[(size_t)NPAD * KP];   // n-major: [Whi ; Wlo ; Whi]
__device__ float g_out[(size_t)NROWS * NPAD];        // projections fp32
__device__ float g_pack[(size_t)B_ * H_ * L_ * PSTEP];

// ---------------------------------------------------------------------------
// Kernel 1a: split inputs A[4096,512] -> A2 bf16 [4096,1536]
// sections: [0,512)=hi, [512,1024)=hi, [1024,1536)=lo   (reads/writes coalesced)
// ---------------------------------------------------------------------------
__global__ void pack_a2_kernel(const float* __restrict__ A) {
    int idx = blockIdx.x * blockDim.x + threadIdx.x;
    if (idx >= NROWS * KP) return;
    int m  = idx / KP;
    int kk = idx - m * KP;
    int k  = (kk < 512) ? kk : ((kk < 1024) ? kk - 512 : kk - 1024);
    float x = A[(size_t)m * D_ + k];
    __nv_bfloat16 hi = __float2bfloat16_rn(x);
    if (kk < 1024) {
        g_A2[idx] = hi;
    } else {
        g_A2[idx] = __float2bfloat16_rn(x - __bfloat162float(hi));
    }
}

// ---------------------------------------------------------------------------
// Kernel 1b: split + transpose weights -> B2T bf16 [1664 (n), 1536 (k)]
// Tiled transpose through smem: reads coalesced along n, writes coalesced
// along k. Each (k,n) element lands at kk=k (hi), 512+k (lo), 1024+k (hi).
// grid: (1664/32, 512/32), block 32x8, 4-row loop.
// ---------------------------------------------------------------------------
__global__ __launch_bounds__(256) void pack_b2t_kernel(const float* __restrict__ Wq,
                                                       const float* __restrict__ Wk,
                                                       const float* __restrict__ Wv,
                                                       const float* __restrict__ Wp) {
    __shared__ float tile[32][33];
    const int n0 = blockIdx.x * 32;
    const int k0 = blockIdx.y * 32;
    const int tx = threadIdx.x;        // 0..31
    const int ty = threadIdx.y;        // 0..7

#pragma unroll
    for (int i = 0; i < 4; i++) {
        int k = k0 + ty + i * 8;
        int n = n0 + tx;
        float x = 0.f;
        if (n < 512)       x = Wq[k * 512 + n];
        else if (n < 1024) x = Wk[k * 512 + (n - 512)];
        else if (n < 1536) x = Wv[k * 512 + (n - 1024)];
        else if (n < 1560) x = Wp[k * 24 + (n - 1536)];
        tile[ty + i * 8][tx] = x;
    }
    __syncthreads();

#pragma unroll
    for (int i = 0; i < 4; i++) {
        int n = n0 + ty + i * 8;
        int k = k0 + tx;
        float x = tile[tx][ty + i * 8];
        __nv_bfloat16 hi = __float2bfloat16_rn(x);
        __nv_bfloat16 lo = __float2bfloat16_rn(x - __bfloat162float(hi));
        __nv_bfloat16* base = g_B2T + (size_t)n * KP;
        base[k]        = hi;
        base[512 + k]  = lo;
        base[1024 + k] = hi;
    }
}

// ---------------------------------------------------------------------------
// Kernel 2: bf16 tensor-core GEMM  C[4096,1664] = A2[4096,1536] @ B2[1536,1664]
// 128x128 CTA tile, 256 threads (8 warps: 4 m x 2 n), warp tile 32m x 64n,
// mma.m16n8k16 row.col. smem row stride 24 bf16 (conflict-free frag LDS).
// ---------------------------------------------------------------------------
#define SSTR 24
__global__ __launch_bounds__(256) void mma_gemm_kernel() {
    __shared__ __align__(16) __nv_bfloat16 As[128 * SSTR];
    __shared__ __align__(16) __nv_bfloat16 Bs[128 * SSTR];
    const int tid  = threadIdx.x;
    const int lane = tid & 31;
    const int wid  = tid >> 5;
    const int wm   = wid >> 1;            // 0..3
    const int wn   = wid & 1;             // 0..1
    const int m0   = blockIdx.y * 128;
    const int n0   = blockIdx.x * 128;
    const int r    = lane >> 2;           // 0..7
    const int cq   = (lane & 3) * 2;      // 0,2,4,6

    float acc[2][8][4];
#pragma unroll
    for (int mt = 0; mt < 2; mt++)
#pragma unroll
        for (int nt = 0; nt < 8; nt++)
#pragma unroll
            for (int u = 0; u < 4; u++) acc[mt][nt][u] = 0.f;

    // global loaders: thread t covers row lr, k-half lh (8 bf16 = 16B)
    const int lr = tid >> 1;
    const int lh = (tid & 1) * 8;
    const __nv_bfloat16* gA = g_A2 + (size_t)(m0 + lr) * KP + lh;
    const __nv_bfloat16* gB = g_B2T + (size_t)(n0 + lr) * KP + lh;

    uint4 av = *(const uint4*)gA;
    uint4 bv = *(const uint4*)gB;

    for (int k0 = 0; k0 < KP; k0 += 16) {
        __syncthreads();   // previous compute done reading smem
        *(uint4*)&As[lr * SSTR + lh] = av;
        *(uint4*)&Bs[lr * SSTR + lh] = bv;
        __syncthreads();

        // prefetch next k-tile (overlaps with compute below)
        if (k0 + 16 < KP) {
            av = *(const uint4*)(gA + k0 + 16);
            bv = *(const uint4*)(gB + k0 + 16);
        }

        // B fragments for this warp's 8 n-tiles
        unsigned int bf0[8], bf1[8];
#pragma unroll
        for (int nt = 0; nt < 8; nt++) {
            int n = wn * 64 + nt * 8 + r;
            bf0[nt] = *(const unsigned int*)&Bs[n * SSTR + cq];
            bf1[nt] = *(const unsigned int*)&Bs[n * SSTR + cq + 8];
        }
#pragma unroll
        for (int mt = 0; mt < 2; mt++) {
            int m = wm * 32 + mt * 16 + r;
            unsigned int a0 = *(const unsigned int*)&As[m * SSTR + cq];
            unsigned int a1 = *(const unsigned int*)&As[(m + 8) * SSTR + cq];
            unsigned int a2 = *(const unsigned int*)&As[m * SSTR + cq + 8];
            unsigned int a3 = *(const unsigned int*)&As[(m + 8) * SSTR + cq + 8];
#pragma unroll
            for (int nt = 0; nt < 8; nt++) {
                asm volatile(
                    "mma.sync.aligned.m16n8k16.row.col.f32.bf16.bf16.f32 "
                    "{%0,%1,%2,%3}, {%4,%5,%6,%7}, {%8,%9}, {%0,%1,%2,%3};"
                    : "+f"(acc[mt][nt][0]), "+f"(acc[mt][nt][1]),
                      "+f"(acc[mt][nt][2]), "+f"(acc[mt][nt][3])
                    : "r"(a0), "r"(a1), "r"(a2), "r"(a3),
                      "r"(bf0[nt]), "r"(bf1[nt]));
            }
        }
    }

    // epilogue
#pragma unroll
    for (int mt = 0; mt < 2; mt++) {
        int row = m0 + wm * 32 + mt * 16 + r;
#pragma unroll
        for (int nt = 0; nt < 8; nt++) {
            int col = n0 + wn * 64 + nt * 8 + cq;
            float* c0 = g_out + (size_t)row * NPAD + col;
            c0[0] = acc[mt][nt][0];
            c0[1] = acc[mt][nt][1];
            float* c2 = c0 + 8 * NPAD;
            c2[0] = acc[mt][nt][2];
            c2[1] = acc[mt][nt][3];
        }
    }
}

// ---------------------------------------------------------------------------
// Kernel 3: postproc — normalize k, compute gates, repack into per-(b,h)
// contiguous stream g_pack[b][h][l] = [q64 | k64 | v64 | gates@192]
// ---------------------------------------------------------------------------
__global__ __launch_bounds__(64) void postproc_kernel(const float* __restrict__ bp) {
    const int row = blockIdx.x;
    const int b = row >> 9, l = row & 511;
    const float* base = g_out + (size_t)row * NPAD;
    const int t  = threadIdx.x;
    const int hh = t >> 3, e8 = t & 7;

    __shared__ float sg[24];
    if (t < 24) {
        float p = base[1536 + t] + bp[t];
        sg[t] = (t < 16) ? (1.0f / (1.0f + expf(-p)))
                         : ((p > 20.f) ? p : log1pf(expf(p)));
    }

    float* dst = g_pack + ((size_t)(b * 8 + hh) * 512 + l) * PSTEP;

    // k: normalize and write
    float kv[8];
    const float* kb = base + 512 + hh * 64 + e8 * 8;
    *(float4*)&kv[0] = *(const float4*)(kb + 0);
    *(float4*)&kv[4] = *(const float4*)(kb + 4);
    float ss = 0.f;
#pragma unroll
    for (int u = 0; u < 8; u++) ss = fmaf(kv[u], kv[u], ss);
    ss += __shfl_xor_sync(0xffffffffu, ss, 1);
    ss += __shfl_xor_sync(0xffffffffu, ss, 2);
    ss += __shfl_xor_sync(0xffffffffu, ss, 4);
    float scale = 1.0f / fmaxf(sqrtf(ss), 1e-12f);
#pragma unroll
    for (int u = 0; u < 8; u++) kv[u] *= scale;
    *(float4*)(dst + 64 + e8 * 8 + 0) = *(float4*)&kv[0];
    *(float4*)(dst + 64 + e8 * 8 + 4) = *(float4*)&kv[4];

    // q copy
    const float* qb = base + hh * 64 + e8 * 8;
    *(float4*)(dst + e8 * 8 + 0) = *(const float4*)(qb + 0);
    *(float4*)(dst + e8 * 8 + 4) = *(const float4*)(qb + 4);

    // v copy
    const float* vb = base + 1024 + hh * 64 + e8 * 8;
    *(float4*)(dst + 128 + e8 * 8 + 0) = *(const float4*)(vb + 0);
    *(float4*)(dst + 128 + e8 * 8 + 4) = *(const float4*)(vb + 4);

    __syncthreads();
    if (e8 < 4) dst[192 + e8] = (e8 < 3) ? sg[e8 * 8 + hh] : 0.f;
}

// ---------------------------------------------------------------------------
// Kernel 4: recurrence (round-5 proven config).
// grid = B*H*16 = 1024 CTAs x 64 threads (2048 warps).
// CTA handles 4 rows of one (b,h). Thread (r = t>>4, c = t&15) owns 4 cols.
// 4-deep register ring with prefetch distance 3 to cover L2/DRAM latency.
// ---------------------------------------------------------------------------
__global__ __launch_bounds__(64) void recurrence_kernel(const float* __restrict__ prev_state,
                                                        const float* __restrict__ prev_mom,
                                                        float* __restrict__ out) {
    const int bid = blockIdx.x;
    const int rb  = bid & 15;
    const int h   = (bid >> 4) & 7;
    const int b   = bid >> 7;
    const int t   = threadIdx.x;
    const int r = t >> 4, c = t & 15;
    const int gi = rb * 4 + r;                  // global state row in [0,64)

    float s[4], m[4];
    {
        const size_t off = ((size_t)((b * 8 + h) * 64 + gi)) * 64 + c * 4;
        *(float4*)&s[0] = *(const float4*)(prev_state + off);
        *(float4*)&m[0] = *(const float4*)(prev_mom + off);
    }

    const float* pbh = g_pack + (size_t)((b * 8 + h) * 512) * PSTEP;
    float* ro  = out + ((size_t)(b * 512) * 8 + h) * 64 + gi;
    float* ssq = out + OFF_S + ((size_t)(b * 512) * 8 + h) * 4096 + (size_t)gi * 64 + c * 4;
    float* msq = ssq + (OFF_M - OFF_S);

    // 4-deep prefetch ring (q, k, v, gates)
    float qb[4][4], kb[4][4], vb[4];
    float4 gb[4];
#pragma unroll
    for (int p = 0; p < 3; p++) {
        const float* sp = pbh + p * PSTEP;
        *(float4*)qb[p] = *(const float4*)(sp + c * 4);
        *(float4*)kb[p] = *(const float4*)(sp + 64 + c * 4);
        vb[p] = sp[128 + gi];
        gb[p] = *(const float4*)(sp + 192);
    }

#pragma unroll 4
    for (int l = 0; l < 512; ++l) {
        const int bi = l & 3;
        const int pi = (l + 3) & 3;
        const int pl = (l + 3 < 512) ? (l + 3) : 511;
        const float* sp = pbh + (size_t)pl * PSTEP;
        // prefetch step l+3 into ring slot pi (never collides with bi)
        *(float4*)qb[pi] = *(const float4*)(sp + c * 4);
        *(float4*)kb[pi] = *(const float4*)(sp + 64 + c * 4);
        vb[pi] = sp[128 + gi];
        gb[pi] = *(const float4*)(sp + 192);

        // partial dot products over owned 4 columns
        float pv = 0.f, py = 0.f;
#pragma unroll
        for (int u = 0; u < 4; u++) {
            pv = fmaf(s[u], kb[bi][u], pv);
            py = fmaf(s[u], qb[bi][u], py);
        }
        // reduce over the 16 lanes of this row (pv/py chains interleave)
        pv += __shfl_xor_sync(0xffffffffu, pv, 1);
        py += __shfl_xor_sync(0xffffffffu, py, 1);
        pv += __shfl_xor_sync(0xffffffffu, pv, 2);
        py += __shfl_xor_sync(0xffffffffu, py, 2);
        pv += __shfl_xor_sync(0xffffffffu, pv, 4);
        py += __shfl_xor_sync(0xffffffffu, py, 4);
        pv += __shfl_xor_sync(0xffffffffu, pv, 8);
        py += __shfl_xor_sync(0xffffffffu, py, 8);

        if (c == 0) __stcs(ro + (size_t)l * 512, py);   // readout: PRE-update state

        const float d   = pv - vb[bi];
        const float td  = gb[bi].z * d;
        const float oma = 1.0f - gb[bi].x;
        const float e   = gb[bi].y;
#pragma unroll
        for (int u = 0; u < 4; u++) {
            m[u] = fmaf(e, m[u], -td * kb[bi][u]);   // eta*mom - theta*grad
            s[u] = fmaf(oma, s[u], m[u]);            // (1-alpha)*state + mom
        }

        __stcs((float4*)(ssq + (size_t)l * 32768), *(float4*)&s[0]);
        __stcs((float4*)(msq + (size_t)l * 32768), *(float4*)&m[0]);
    }
}

// ---------------------------------------------------------------------------
// Launch
// ---------------------------------------------------------------------------
extern "C" void kernel_launch(void* const* d_in, const int* in_sizes, int n_in,
                              void* d_out, int out_size) {
    const float* inputs   = (const float*)d_in[0];
    const float* Wq       = (const float*)d_in[1];
    const float* Wk       = (const float*)d_in[2];
    const float* Wv       = (const float*)d_in[3];
    const float* Wp       = (const float*)d_in[4];
    const float* bp       = (const float*)d_in[5];
    const float* prev_st  = (const float*)d_in[6];
    const float* prev_mom = (const float*)d_in[7];
    float* out = (float*)d_out;

    pack_a2_kernel<<<(NROWS * KP + 255) / 256, 256>>>(inputs);
    pack_b2t_kernel<<<dim3(NPAD / 32, D_ / 32), dim3(32, 8)>>>(Wq, Wk, Wv, Wp);
    mma_gemm_kernel<<<dim3(NPAD / 128, NROWS / 128), 256>>>();
    postproc_kernel<<<NROWS, 64>>>(bp);
    recurrence_kernel<<<B_ * H_ * 16, 64>>>(prev_st, prev_mom, out);
}

// round 12
// speedup vs baseline: 1.2528x; 1.2528x over previous
#include <cuda_runtime.h>
#include <cuda_bf16.h>
#include <math.h>

// Problem dims
#define B_ 8
#define L_ 512
#define D_ 512
#define H_ 8
#define DH_ 64
#define NROWS 4096          // B*L
#define NPAD 1664           // 13*128 GEMM N (q512|k512|v512|p24|pad)
#define KP 1536             // split-GEMM K' = 3*512

// Output layout (concatenated fp32): readout | state_seq | mom_seq
#define OFF_S 2097152UL
#define OFF_M 136314880UL

// Packed per-(b,h) stream: [q(64) | k_norm(64) | v(64) | a,e,th,pad] per step
#define PSTEP 196

// Scratch (static device arrays — no allocation)
__device__ __nv_bfloat16 g_A2[(size_t)NROWS * KP];   // [Ahi | Ahi | Alo] rows
__device__ __nv_bfloat16 g_B2T[(size_t)NPAD * KP];   // n-major: [Whi ; Wlo ; Whi]
__device__ float g_p[(size_t)NROWS * 24];            // raw gate logits
__device__ float g_pack[(size_t)B_ * H_ * L_ * PSTEP];

// ---------------------------------------------------------------------------
// Kernel 1a: split inputs A[4096,512] -> A2 bf16 [4096,1536]
// sections: [0,512)=hi, [512,1024)=hi, [1024,1536)=lo
// ---------------------------------------------------------------------------
__global__ void pack_a2_kernel(const float* __restrict__ A) {
    int idx = blockIdx.x * blockDim.x + threadIdx.x;
    if (idx >= NROWS * KP) return;
    int m  = idx / KP;
    int kk = idx - m * KP;
    int k  = (kk < 512) ? kk : ((kk < 1024) ? kk - 512 : kk - 1024);
    float x = A[(size_t)m * D_ + k];
    __nv_bfloat16 hi = __float2bfloat16_rn(x);
    if (kk < 1024) {
        g_A2[idx] = hi;
    } else {
        g_A2[idx] = __float2bfloat16_rn(x - __bfloat162float(hi));
    }
}

// ---------------------------------------------------------------------------
// Kernel 1b: split + transpose weights -> B2T bf16 [1664 (n), 1536 (k)]
// Tiled transpose through smem (coalesced both sides).
// ---------------------------------------------------------------------------
__global__ __launch_bounds__(256) void pack_b2t_kernel(const float* __restrict__ Wq,
                                                       const float* __restrict__ Wk,
                                                       const float* __restrict__ Wv,
                                                       const float* __restrict__ Wp) {
    __shared__ float tile[32][33];
    const int n0 = blockIdx.x * 32;
    const int k0 = blockIdx.y * 32;
    const int tx = threadIdx.x;        // 0..31
    const int ty = threadIdx.y;        // 0..7

#pragma unroll
    for (int i = 0; i < 4; i++) {
        int k = k0 + ty + i * 8;
        int n = n0 + tx;
        float x = 0.f;
        if (n < 512)       x = Wq[k * 512 + n];
        else if (n < 1024) x = Wk[k * 512 + (n - 512)];
        else if (n < 1536) x = Wv[k * 512 + (n - 1024)];
        else if (n < 1560) x = Wp[k * 24 + (n - 1536)];
        tile[ty + i * 8][tx] = x;
    }
    __syncthreads();

#pragma unroll
    for (int i = 0; i < 4; i++) {
        int n = n0 + ty + i * 8;
        int k = k0 + tx;
        float x = tile[tx][ty + i * 8];
        __nv_bfloat16 hi = __float2bfloat16_rn(x);
        __nv_bfloat16 lo = __float2bfloat16_rn(x - __bfloat162float(hi));
        __nv_bfloat16* base = g_B2T + (size_t)n * KP;
        base[k]        = hi;
        base[512 + k]  = lo;
        base[1024 + k] = hi;
    }
}

// ---------------------------------------------------------------------------
// Kernel 2: bf16 tensor-core GEMM with FUSED epilogue.
// C[4096,1664] = A2 @ B2. 128x128 CTA tile, 8 warps (4m x 2n), warp tile
// 32m x 64n = exactly one head per warp n-span.
// Epilogue routes directly into g_pack:
//   n-tiles 0-3: q -> dst+0..63
//   n-tiles 4-7: k -> L2-normalize per row (in-register + 2 shfls) -> dst+64
//   n-tiles 8-11: v -> dst+128
//   n-tile 12: raw gate logits (24 cols) -> g_p
// ---------------------------------------------------------------------------
#define SSTR 24
__global__ __launch_bounds__(256) void mma_gemm_kernel() {
    __shared__ __align__(16) __nv_bfloat16 As[128 * SSTR];
    __shared__ __align__(16) __nv_bfloat16 Bs[128 * SSTR];
    const int tid  = threadIdx.x;
    const int lane = tid & 31;
    const int wid  = tid >> 5;
    const int wm   = wid >> 1;            // 0..3
    const int wn   = wid & 1;             // 0..1
    const int m0   = blockIdx.y * 128;
    const int n0   = blockIdx.x * 128;
    const int r    = lane >> 2;           // 0..7
    const int cq   = (lane & 3) * 2;      // 0,2,4,6

    float acc[2][8][4];
#pragma unroll
    for (int mt = 0; mt < 2; mt++)
#pragma unroll
        for (int nt = 0; nt < 8; nt++)
#pragma unroll
            for (int u = 0; u < 4; u++) acc[mt][nt][u] = 0.f;

    // global loaders: thread t covers row lr, k-half lh (8 bf16 = 16B)
    const int lr = tid >> 1;
    const int lh = (tid & 1) * 8;
    const __nv_bfloat16* gA = g_A2 + (size_t)(m0 + lr) * KP + lh;
    const __nv_bfloat16* gB = g_B2T + (size_t)(n0 + lr) * KP + lh;

    uint4 av = *(const uint4*)gA;
    uint4 bv = *(const uint4*)gB;

    for (int k0 = 0; k0 < KP; k0 += 16) {
        __syncthreads();
        *(uint4*)&As[lr * SSTR + lh] = av;
        *(uint4*)&Bs[lr * SSTR + lh] = bv;
        __syncthreads();

        if (k0 + 16 < KP) {
            av = *(const uint4*)(gA + k0 + 16);
            bv = *(const uint4*)(gB + k0 + 16);
        }

        unsigned int bf0[8], bf1[8];
#pragma unroll
        for (int nt = 0; nt < 8; nt++) {
            int n = wn * 64 + nt * 8 + r;
            bf0[nt] = *(const unsigned int*)&Bs[n * SSTR + cq];
            bf1[nt] = *(const unsigned int*)&Bs[n * SSTR + cq + 8];
        }
#pragma unroll
        for (int mt = 0; mt < 2; mt++) {
            int m = wm * 32 + mt * 16 + r;
            unsigned int a0 = *(const unsigned int*)&As[m * SSTR + cq];
            unsigned int a1 = *(const unsigned int*)&As[(m + 8) * SSTR + cq];
            unsigned int a2 = *(const unsigned int*)&As[m * SSTR + cq + 8];
            unsigned int a3 = *(const unsigned int*)&As[(m + 8) * SSTR + cq + 8];
#pragma unroll
            for (int nt = 0; nt < 8; nt++) {
                asm volatile(
                    "mma.sync.aligned.m16n8k16.row.col.f32.bf16.bf16.f32 "
                    "{%0,%1,%2,%3}, {%4,%5,%6,%7}, {%8,%9}, {%0,%1,%2,%3};"
                    : "+f"(acc[mt][nt][0]), "+f"(acc[mt][nt][1]),
                      "+f"(acc[mt][nt][2]), "+f"(acc[mt][nt][3])
                    : "r"(a0), "r"(a1), "r"(a2), "r"(a3),
                      "r"(bf0[nt]), "r"(bf1[nt]));
            }
        }
    }

    // ---------------- fused epilogue ----------------
    const int nx = blockIdx.x;
    if (nx < 12) {
        const int region = nx >> 2;               // 0=q, 1=k, 2=v
        const int off    = region * 64;           // offset within pack step
        const int h      = (nx & 3) * 2 + wn;     // head index 0..7

#pragma unroll
        for (int mt = 0; mt < 2; mt++) {
            const int mA = m0 + wm * 32 + mt * 16 + r;      // row for acc[.][.][0,1]
            const int mB = mA + 8;                          // row for acc[.][.][2,3]

            float sc0 = 1.f, sc1 = 1.f;
            if (region == 1) {
                // k: per-row L2 norm over this warp's 64 cols
                float ss0 = 0.f, ss1 = 0.f;
#pragma unroll
                for (int nt = 0; nt < 8; nt++) {
                    ss0 = fmaf(acc[mt][nt][0], acc[mt][nt][0], ss0);
                    ss0 = fmaf(acc[mt][nt][1], acc[mt][nt][1], ss0);
                    ss1 = fmaf(acc[mt][nt][2], acc[mt][nt][2], ss1);
                    ss1 = fmaf(acc[mt][nt][3], acc[mt][nt][3], ss1);
                }
                ss0 += __shfl_xor_sync(0xffffffffu, ss0, 1);
                ss1 += __shfl_xor_sync(0xffffffffu, ss1, 1);
                ss0 += __shfl_xor_sync(0xffffffffu, ss0, 2);
                ss1 += __shfl_xor_sync(0xffffffffu, ss1, 2);
                sc0 = 1.0f / fmaxf(sqrtf(ss0), 1e-12f);
                sc1 = 1.0f / fmaxf(sqrtf(ss1), 1e-12f);
            }

            const int bA = mA >> 9, lA = mA & 511;
            const int bB = mB >> 9, lB = mB & 511;
            float* dA = g_pack + ((size_t)(bA * 8 + h) * 512 + lA) * PSTEP + off + cq;
            float* dB = g_pack + ((size_t)(bB * 8 + h) * 512 + lB) * PSTEP + off + cq;
#pragma unroll
            for (int nt = 0; nt < 8; nt++) {
                *(float2*)(dA + nt * 8) = make_float2(acc[mt][nt][0] * sc0,
                                                      acc[mt][nt][1] * sc0);
                *(float2*)(dB + nt * 8) = make_float2(acc[mt][nt][2] * sc1,
                                                      acc[mt][nt][3] * sc1);
            }
        }
    } else {
        // p tile: cols 0..23 valid (wn==0, nt<3)
        if (wn == 0) {
#pragma unroll
            for (int mt = 0; mt < 2; mt++) {
                const int mA = m0 + wm * 32 + mt * 16 + r;
                const int mB = mA + 8;
#pragma unroll
                for (int nt = 0; nt < 3; nt++) {
                    int cp = nt * 8 + cq;
                    if (cp < 24) {
                        float* pA = g_p + (size_t)mA * 24 + cp;
                        float* pB = g_p + (size_t)mB * 24 + cp;
                        pA[0] = acc[mt][nt][0];
                        if (cp + 1 < 24) pA[1] = acc[mt][nt][1];
                        pB[0] = acc[mt][nt][2];
                        if (cp + 1 < 24) pB[1] = acc[mt][nt][3];
                    }
                }
            }
        }
    }
}

// ---------------------------------------------------------------------------
// Kernel 3: gates — sigmoid/softplus on raw logits, scatter into g_pack.
// 4096 rows x 24 logits; t%8 = head, t/8 = slot (alpha/eta/theta).
// ---------------------------------------------------------------------------
__global__ __launch_bounds__(256) void gates_kernel(const float* __restrict__ bp) {
    int idx = blockIdx.x * blockDim.x + threadIdx.x;
    if (idx >= NROWS * 24) return;
    int row = idx / 24;
    int t   = idx - row * 24;
    int b = row >> 9, l = row & 511;
    int slot = t >> 3, h = t & 7;
    float p = g_p[idx] + bp[t];
    float g = (slot < 2) ? (1.0f / (1.0f + expf(-p)))
                         : ((p > 20.f) ? p : log1pf(expf(p)));
    g_pack[((size_t)(b * 8 + h) * 512 + l) * PSTEP + 192 + slot] = g;
}

// ---------------------------------------------------------------------------
// Kernel 4: recurrence (round-5/9 proven config, PSTEP=196).
// grid = B*H*16 = 1024 CTAs x 64 threads (2048 warps).
// CTA handles 4 rows of one (b,h). Thread (r = t>>4, c = t&15) owns 4 cols.
// 4-deep register ring with prefetch distance 3 to cover L2/DRAM latency.
// ---------------------------------------------------------------------------
__global__ __launch_bounds__(64) void recurrence_kernel(const float* __restrict__ prev_state,
                                                        const float* __restrict__ prev_mom,
                                                        float* __restrict__ out) {
    const int bid = blockIdx.x;
    const int rb  = bid & 15;
    const int h   = (bid >> 4) & 7;
    const int b   = bid >> 7;
    const int t   = threadIdx.x;
    const int r = t >> 4, c = t & 15;
    const int gi = rb * 4 + r;                  // global state row in [0,64)

    float s[4], m[4];
    {
        const size_t off = ((size_t)((b * 8 + h) * 64 + gi)) * 64 + c * 4;
        *(float4*)&s[0] = *(const float4*)(prev_state + off);
        *(float4*)&m[0] = *(const float4*)(prev_mom + off);
    }

    const float* pbh = g_pack + (size_t)((b * 8 + h) * 512) * PSTEP;
    float* ro  = out + ((size_t)(b * 512) * 8 + h) * 64 + gi;
    float* ssq = out + OFF_S + ((size_t)(b * 512) * 8 + h) * 4096 + (size_t)gi * 64 + c * 4;
    float* msq = ssq + (OFF_M - OFF_S);

    // 4-deep prefetch ring (q, k, v, gates)
    float qb[4][4], kb[4][4], vb[4];
    float4 gb[4];
#pragma unroll
    for (int p = 0; p < 3; p++) {
        const float* sp = pbh + p * PSTEP;
        *(float4*)qb[p] = *(const float4*)(sp + c * 4);
        *(float4*)kb[p] = *(const float4*)(sp + 64 + c * 4);
        vb[p] = sp[128 + gi];
        gb[p] = *(const float4*)(sp + 192);
    }

#pragma unroll 4
    for (int l = 0; l < 512; ++l) {
        const int bi = l & 3;
        const int pi = (l + 3) & 3;
        const int pl = (l + 3 < 512) ? (l + 3) : 511;
        const float* sp = pbh + (size_t)pl * PSTEP;
        // prefetch step l+3 into ring slot pi (never collides with bi)
        *(float4*)qb[pi] = *(const float4*)(sp + c * 4);
        *(float4*)kb[pi] = *(const float4*)(sp + 64 + c * 4);
        vb[pi] = sp[128 + gi];
        gb[pi] = *(const float4*)(sp + 192);

        // partial dot products over owned 4 columns
        float pv = 0.f, py = 0.f;
#pragma unroll
        for (int u = 0; u < 4; u++) {
            pv = fmaf(s[u], kb[bi][u], pv);
            py = fmaf(s[u], qb[bi][u], py);
        }
        // reduce over the 16 lanes of this row (pv/py chains interleave)
        pv += __shfl_xor_sync(0xffffffffu, pv, 1);
        py += __shfl_xor_sync(0xffffffffu, py, 1);
        pv += __shfl_xor_sync(0xffffffffu, pv, 2);
        py += __shfl_xor_sync(0xffffffffu, py, 2);
        pv += __shfl_xor_sync(0xffffffffu, pv, 4);
        py += __shfl_xor_sync(0xffffffffu, py, 4);
        pv += __shfl_xor_sync(0xffffffffu, pv, 8);
        py += __shfl_xor_sync(0xffffffffu, py, 8);

        if (c == 0) __stcs(ro + (size_t)l * 512, py);   // readout: PRE-update state

        const float d   = pv - vb[bi];
        const float td  = gb[bi].z * d;
        const float oma = 1.0f - gb[bi].x;
        const float e   = gb[bi].y;
#pragma unroll
        for (int u = 0; u < 4; u++) {
            m[u] = fmaf(e, m[u], -td * kb[bi][u]);   // eta*mom - theta*grad
            s[u] = fmaf(oma, s[u], m[u]);            // (1-alpha)*state + mom
        }

        __stcs((float4*)(ssq + (size_t)l * 32768), *(float4*)&s[0]);
        __stcs((float4*)(msq + (size_t)l * 32768), *(float4*)&m[0]);
    }
}

// ---------------------------------------------------------------------------
// Launch
// ---------------------------------------------------------------------------
extern "C" void kernel_launch(void* const* d_in, const int* in_sizes, int n_in,
                              void* d_out, int out_size) {
    const float* inputs   = (const float*)d_in[0];
    const float* Wq       = (const float*)d_in[1];
    const float* Wk       = (const float*)d_in[2];
    const float* Wv       = (const float*)d_in[3];
    const float* Wp       = (const float*)d_in[4];
    const float* bp       = (const float*)d_in[5];
    const float* prev_st  = (const float*)d_in[6];
    const float* prev_mom = (const float*)d_in[7];
    float* out = (float*)d_out;

    pack_a2_kernel<<<(NROWS * KP + 255) / 256, 256>>>(inputs);
    pack_b2t_kernel<<<dim3(NPAD / 32, D_ / 32), dim3(32, 8)>>>(Wq, Wk, Wv, Wp);
    mma_gemm_kernel<<<dim3(NPAD / 128, NROWS / 128), 256>>>();
    gates_kernel<<<(NROWS * 24 + 255) / 256, 256>>>(bp);
    recurrence_kernel<<<B_ * H_ * 16, 64>>>(prev_st, prev_mom, out);
}